// round 2
// baseline (speedup 1.0000x reference)
#include <cuda_runtime.h>
#include <math.h>

#define FULLMASK 0xffffffffu
#define INV_SIGMA 200.0f   // 1/0.005

// scratch: row norms (device globals; no runtime allocation allowed)
__device__ float g_a2[4 * 4096];   // |f1_n|^2
__device__ float g_b2[4 * 4096];   // |f2_m|^2
__device__ float g_p2[4 * 4096];   // |points_n * 200|^2

__global__ void zero_k(float* out, int n) {
    int i = threadIdx.x;
    if (i < n) out[i] = 0.0f;
}

// Precompute norms + reg loss. One thread per (b,n).
__global__ void init_norms(const float* __restrict__ points,
                           const float* __restrict__ f1,
                           const float* __restrict__ f2,
                           float* __restrict__ out,
                           int B, int N, int D) {
    int idx = blockIdx.x * blockDim.x + threadIdx.x;
    if (idx >= B * N) return;
    int b = idx / N;
    const float4* pa = (const float4*)(f1 + (size_t)idx * D);
    const float4* pb = (const float4*)(f2 + (size_t)idx * D);
    float a2 = 0.f, b2 = 0.f;
    int nd4 = D >> 2;
    #pragma unroll 16
    for (int i = 0; i < nd4; i++) {
        float4 v = pa[i];
        a2 = fmaf(v.x, v.x, a2); a2 = fmaf(v.y, v.y, a2);
        a2 = fmaf(v.z, v.z, a2); a2 = fmaf(v.w, v.w, a2);
        float4 u = pb[i];
        b2 = fmaf(u.x, u.x, b2); b2 = fmaf(u.y, u.y, b2);
        b2 = fmaf(u.z, u.z, b2); b2 = fmaf(u.w, u.w, b2);
    }
    g_a2[idx] = a2;
    g_b2[idx] = b2;
    float px = points[idx * 3 + 0] * INV_SIGMA;
    float py = points[idx * 3 + 1] * INV_SIGMA;
    float pz = points[idx * 3 + 2] * INV_SIGMA;
    g_p2[idx] = px * px + py * py + pz * pz;

    // reg[b] = mean_n mean_d (f1^2 + f2^2) = sum(a2+b2)/(N*D)
    float val = a2 + b2;
    #pragma unroll
    for (int o = 16; o; o >>= 1) val += __shfl_xor_sync(FULLMASK, val, o);
    if ((threadIdx.x & 31) == 0)
        atomicAdd(&out[B + b], val / (float)(N * D));
}

__device__ __forceinline__ float redmax16(float v) {
    v = fmaxf(v, __shfl_xor_sync(FULLMASK, v, 1));
    v = fmaxf(v, __shfl_xor_sync(FULLMASK, v, 2));
    v = fmaxf(v, __shfl_xor_sync(FULLMASK, v, 4));
    v = fmaxf(v, __shfl_xor_sync(FULLMASK, v, 8));
    return v;
}
__device__ __forceinline__ float redsum16(float v) {
    v += __shfl_xor_sync(FULLMASK, v, 1);
    v += __shfl_xor_sync(FULLMASK, v, 2);
    v += __shfl_xor_sync(FULLMASK, v, 4);
    v += __shfl_xor_sync(FULLMASK, v, 8);
    return v;
}

// Main fused kernel: CTA = 64 rows of one batch, loop over all m in 64-chunks.
// 256 threads, thread (tx,ty) owns rows ty*4..+3, cols tx*4..+3 of each block.
__global__ void __launch_bounds__(256, 2)
loss_main(const float* __restrict__ points,
          const float* __restrict__ f1,
          const float* __restrict__ f2,
          const float* __restrict__ wts,
          float* __restrict__ out, int N) {
    __shared__ float As[64][68];   // f1 tile, n-major (pad 68: aligned float4, broadcast reads)
    __shared__ float Bs[64][64];   // f2 chunk, k-major (transposed on store)
    __shared__ float sred[16];

    const int b   = blockIdx.y;
    const int n0  = blockIdx.x * 64;
    const int tid = threadIdx.x;
    const int tx  = tid & 15;
    const int ty  = tid >> 4;
    const size_t base = (size_t)b * N;

    // ---- load A tile (once per CTA) ----
    #pragma unroll
    for (int it = 0; it < 4; it++) {
        int ln = it * 256 + tid;
        int n = ln >> 4, d4 = ln & 15;
        float4 v = *(const float4*)(f1 + (base + n0 + n) * 64 + d4 * 4);
        *(float4*)&As[n][d4 * 4] = v;
    }

    // ---- per-row constants ----
    float ra2[4], rp2[4], prx[4], pry[4], prz[4];
    #pragma unroll
    for (int i = 0; i < 4; i++) {
        int n = n0 + ty * 4 + i;
        ra2[i] = g_a2[base + n];
        rp2[i] = g_p2[base + n];
        prx[i] = points[(base + n) * 3 + 0] * INV_SIGMA;
        pry[i] = points[(base + n) * 3 + 1] * INV_SIGMA;
        prz[i] = points[(base + n) * 3 + 2] * INV_SIGMA;
    }

    // running online-softmax stats per row
    float rfmax[4], rfsum[4], rpmax[4], rpsum[4], rT[4];
    #pragma unroll
    for (int i = 0; i < 4; i++) {
        rfmax[i] = -1e30f; rpmax[i] = -1e30f;
        rfsum[i] = 0.f; rpsum[i] = 0.f; rT[i] = 0.f;
    }

    for (int m0 = 0; m0 < N; m0 += 64) {
        __syncthreads();
        // load B chunk, transposed to k-major
        #pragma unroll
        for (int it = 0; it < 4; it++) {
            int ln = it * 256 + tid;
            int m = ln >> 4, d4 = ln & 15;
            float4 v = *(const float4*)(f2 + (base + m0 + m) * 64 + d4 * 4);
            Bs[d4 * 4 + 0][m] = v.x;
            Bs[d4 * 4 + 1][m] = v.y;
            Bs[d4 * 4 + 2][m] = v.z;
            Bs[d4 * 4 + 3][m] = v.w;
        }
        __syncthreads();

        // ---- 64-deep feature dot, 4x4 micro-tile ----
        float fa[4][4];
        #pragma unroll
        for (int i = 0; i < 4; i++)
            #pragma unroll
            for (int j = 0; j < 4; j++) fa[i][j] = 0.f;

        #pragma unroll
        for (int k0 = 0; k0 < 64; k0 += 4) {
            float a_[4][4];
            #pragma unroll
            for (int i = 0; i < 4; i++)
                *(float4*)&a_[i][0] = *(const float4*)&As[ty * 4 + i][k0];
            #pragma unroll
            for (int kk = 0; kk < 4; kk++) {
                float4 bv = *(const float4*)&Bs[k0 + kk][tx * 4];
                float bb[4] = {bv.x, bv.y, bv.z, bv.w};
                #pragma unroll
                for (int i = 0; i < 4; i++)
                    #pragma unroll
                    for (int j = 0; j < 4; j++)
                        fa[i][j] = fmaf(a_[i][kk], bb[j], fa[i][j]);
            }
        }

        // ---- per-column constants ----
        float cb2[4], cp2[4], pcx[4], pcy[4], pcz[4];
        #pragma unroll
        for (int j = 0; j < 4; j++) {
            int m = m0 + tx * 4 + j;
            cb2[j] = g_b2[base + m];
            cp2[j] = g_p2[base + m];
            pcx[j] = points[(base + m) * 3 + 0] * INV_SIGMA;
            pcy[j] = points[(base + m) * 3 + 1] * INV_SIGMA;
            pcz[j] = points[(base + m) * 3 + 2] * INV_SIGMA;
        }

        // ---- online softmax update per row ----
        #pragma unroll
        for (int i = 0; i < 4; i++) {
            float fd[4], pd[4];
            #pragma unroll
            for (int j = 0; j < 4; j++) {
                fd[j] = 2.f * fa[i][j] - ra2[i] - cb2[j];
                float pdot = prx[i] * pcx[j];
                pdot = fmaf(pry[i], pcy[j], pdot);
                pdot = fmaf(prz[i], pcz[j], pdot);
                pd[j] = 2.f * pdot - rp2[i] - cp2[j];
            }
            float cfm = fmaxf(fmaxf(fd[0], fd[1]), fmaxf(fd[2], fd[3]));
            cfm = redmax16(cfm);
            float cpm = fmaxf(fmaxf(pd[0], pd[1]), fmaxf(pd[2], pd[3]));
            cpm = redmax16(cpm);

            float sf = 0.f, sp = 0.f, st = 0.f;
            #pragma unroll
            for (int j = 0; j < 4; j++) {
                float ef = __expf(fd[j] - cfm);
                sf += ef;
                float ep = __expf(pd[j] - cpm);
                sp += ep;
                st = fmaf(ep, fd[j], st);
            }
            sf = redsum16(sf);
            sp = redsum16(sp);
            st = redsum16(st);

            // merge chunk stats into running stats (branchless rescale)
            float nf = fmaxf(rfmax[i], cfm);
            rfsum[i] = rfsum[i] * __expf(rfmax[i] - nf) + sf * __expf(cfm - nf);
            rfmax[i] = nf;
            float np = fmaxf(rpmax[i], cpm);
            float s1 = __expf(rpmax[i] - np);
            float s2 = __expf(cpm - np);
            rpsum[i] = rpsum[i] * s1 + sp * s2;
            rT[i]    = rT[i]    * s1 + st * s2;
            rpmax[i] = np;
        }
    }

    // ---- epilogue: ce_n = w_n * (lseF_n - T_n/psum_n), reduce over CTA ----
    if (tx == 0) {
        float ce = 0.f;
        #pragma unroll
        for (int i = 0; i < 4; i++) {
            int n = n0 + ty * 4 + i;
            float lse = rfmax[i] + logf(rfsum[i]);
            ce += wts[base + n] * (lse - rT[i] / rpsum[i]);
        }
        sred[ty] = ce;
    }
    __syncthreads();
    if (tid == 0) {
        float s = 0.f;
        #pragma unroll
        for (int t = 0; t < 16; t++) s += sred[t];
        atomicAdd(&out[b], s);
    }
}

extern "C" void kernel_launch(void* const* d_in, const int* in_sizes, int n_in,
                              void* d_out, int out_size) {
    const float* points = (const float*)d_in[0];
    const float* f1     = (const float*)d_in[1];
    const float* f2     = (const float*)d_in[2];
    const float* w      = (const float*)d_in[3];
    float* out = (float*)d_out;

    int B = out_size / 2;                 // out = [ce_loss(B), reg(B)]
    int N = in_sizes[3] / B;              // weights is B*N
    int D = in_sizes[1] / (B * N);        // 64

    zero_k<<<1, 32>>>(out, out_size);
    init_norms<<<(B * N + 255) / 256, 256>>>(points, f1, f2, out, B, N, D);
    dim3 grid(N / 64, B);
    loss_main<<<grid, 256>>>(points, f1, f2, w, out, N);
}

// round 4
// speedup vs baseline: 1.5425x; 1.5425x over previous
#include <cuda_runtime.h>
#include <math.h>

#define FULLMASK 0xffffffffu
#define INV_SIGMA 200.0f   // 1/0.005

// device scratch (no runtime allocation allowed)
__device__ float  g_a2[4 * 4096];    // |f1_n|^2
__device__ float  g_b2[4 * 4096];    // |f2_m|^2
__device__ float4 g_pts[4 * 4096];   // (x*s, y*s, z*s, |p*s|^2)

// ---- packed fp32x2 helpers (Blackwell FFMA2; PTX-only) ----
__device__ __forceinline__ void fma2(unsigned long long& d,
                                     unsigned long long a,
                                     unsigned long long b) {
    asm("fma.rn.f32x2 %0, %1, %2, %0;" : "+l"(d) : "l"(a), "l"(b));
}
__device__ __forceinline__ unsigned long long pack2(float x) {
    unsigned long long r;
    unsigned int u = __float_as_uint(x);
    asm("mov.b64 %0, {%1, %2};" : "=l"(r) : "r"(u), "r"(u));
    return r;
}
__device__ __forceinline__ void unpack2(float& lo, float& hi, unsigned long long v) {
    unsigned int a, b;
    asm("mov.b64 {%0, %1}, %2;" : "=r"(a), "=r"(b) : "l"(v));
    lo = __uint_as_float(a);
    hi = __uint_as_float(b);
}

__global__ void zero_k(float* out, int n) {
    int i = threadIdx.x;
    if (i < n) out[i] = 0.0f;
}

// Precompute norms, scaled points, and the reg loss. One thread per (b,n).
__global__ void init_norms(const float* __restrict__ points,
                           const float* __restrict__ f1,
                           const float* __restrict__ f2,
                           float* __restrict__ out,
                           int B, int N, int D) {
    int idx = blockIdx.x * blockDim.x + threadIdx.x;
    if (idx >= B * N) return;
    int b = idx / N;
    const float4* pa = (const float4*)(f1 + (size_t)idx * D);
    const float4* pb = (const float4*)(f2 + (size_t)idx * D);
    float a2 = 0.f, b2 = 0.f;
    int nd4 = D >> 2;
    #pragma unroll 16
    for (int i = 0; i < nd4; i++) {
        float4 v = pa[i];
        a2 = fmaf(v.x, v.x, a2); a2 = fmaf(v.y, v.y, a2);
        a2 = fmaf(v.z, v.z, a2); a2 = fmaf(v.w, v.w, a2);
        float4 u = pb[i];
        b2 = fmaf(u.x, u.x, b2); b2 = fmaf(u.y, u.y, b2);
        b2 = fmaf(u.z, u.z, b2); b2 = fmaf(u.w, u.w, b2);
    }
    g_a2[idx] = a2;
    g_b2[idx] = b2;
    float px = points[idx * 3 + 0] * INV_SIGMA;
    float py = points[idx * 3 + 1] * INV_SIGMA;
    float pz = points[idx * 3 + 2] * INV_SIGMA;
    float p2 = px * px + py * py + pz * pz;
    g_pts[idx] = make_float4(px, py, pz, p2);

    // reg[b] = sum(a2+b2)/(N*D)
    float val = a2 + b2;
    #pragma unroll
    for (int o = 16; o; o >>= 1) val += __shfl_xor_sync(FULLMASK, val, o);
    if ((threadIdx.x & 31) == 0)
        atomicAdd(&out[B + b], val / (float)(N * D));
}

__device__ __forceinline__ float redmax16(float v) {
    v = fmaxf(v, __shfl_xor_sync(FULLMASK, v, 1));
    v = fmaxf(v, __shfl_xor_sync(FULLMASK, v, 2));
    v = fmaxf(v, __shfl_xor_sync(FULLMASK, v, 4));
    v = fmaxf(v, __shfl_xor_sync(FULLMASK, v, 8));
    return v;
}
__device__ __forceinline__ float redsum16(float v) {
    v += __shfl_xor_sync(FULLMASK, v, 1);
    v += __shfl_xor_sync(FULLMASK, v, 2);
    v += __shfl_xor_sync(FULLMASK, v, 4);
    v += __shfl_xor_sync(FULLMASK, v, 8);
    return v;
}

// Main fused kernel: CTA = 64 rows of one batch, m-loop in 64-chunks.
// 256 threads; thread (tx,ty) owns rows ty*4..+3, cols tx*4..+3.
// B tile is k-major with XOR granule swizzle: element (k,m) lives at
//   Bs[k*64 + (((m>>2) ^ (k>>2)) << 2) + (m&3)]
// -> transpose stores are 2-way conflicted, pair reads are conflict-free
//    and 16B aligned (ulonglong2 -> f32x2 operands with zero packing).
__global__ void __launch_bounds__(256, 2)
loss_main(const float* __restrict__ f1,
          const float* __restrict__ f2,
          const float* __restrict__ wts,
          float* __restrict__ out, int N) {
    __shared__ __align__(16) float As[64][68];
    __shared__ __align__(16) float Bs[64 * 64];
    __shared__ float sred[16];

    const int b   = blockIdx.y;
    const int n0  = blockIdx.x * 64;
    const int tid = threadIdx.x;
    const int tx  = tid & 15;
    const int ty  = tid >> 4;
    const size_t base = (size_t)b * N;

    // ---- load A tile (once per CTA) ----
    #pragma unroll
    for (int it = 0; it < 4; it++) {
        int n = it * 16 + ty;
        float4 v = *(const float4*)(f1 + (base + n0 + n) * 64 + tx * 4);
        *(float4*)&As[n][tx * 4] = v;
    }

    // ---- per-row constants ----
    float nra2[4], nrp2[4], prx[4], pry[4], prz[4];
    #pragma unroll
    for (int i = 0; i < 4; i++) {
        int n = n0 + ty * 4 + i;
        nra2[i] = -g_a2[base + n];
        float4 p = g_pts[base + n];
        prx[i] = p.x; pry[i] = p.y; prz[i] = p.z;
        nrp2[i] = -p.w;
    }

    // per-thread private online-softmax stats (merged across lanes at the end)
    float rfmax[4], rfsum[4], rpsum[4], rT[4];
    #pragma unroll
    for (int i = 0; i < 4; i++) {
        rfmax[i] = -1e30f; rfsum[i] = 0.f; rpsum[i] = 0.f; rT[i] = 0.f;
    }

    const int nCh = N >> 6;

    // prefetch chunk 0 into registers
    float4 bv[4];
    #pragma unroll
    for (int it = 0; it < 4; it++) {
        int m = it * 16 + ty;
        bv[it] = *(const float4*)(f2 + (base + m) * 64 + tx * 4);
    }

    for (int c = 0; c < nCh; c++) {
        __syncthreads();   // prior chunk's readers are done with Bs
        // ---- store prefetched B chunk, swizzled transpose ----
        #pragma unroll
        for (int it = 0; it < 4; it++) {
            int m = it * 16 + ty;
            int col = (((m >> 2) ^ tx) << 2) + (m & 3);
            float* p = &Bs[(tx * 4) * 64 + col];
            float4 v = bv[it];
            p[0]   = v.x;
            p[64]  = v.y;
            p[128] = v.z;
            p[192] = v.w;
        }
        __syncthreads();   // Bs visible to all

        // prefetch next chunk (latency hidden under the GEMM)
        if (c + 1 < nCh) {
            #pragma unroll
            for (int it = 0; it < 4; it++) {
                int m = (c + 1) * 64 + it * 16 + ty;
                bv[it] = *(const float4*)(f2 + (base + m) * 64 + tx * 4);
            }
        }

        // ---- per-column constants for this chunk ----
        float nb[4], npc[4], pcx[4], pcy[4], pcz[4];
        #pragma unroll
        for (int j = 0; j < 4; j++) {
            int m = c * 64 + tx * 4 + j;
            nb[j] = -g_b2[base + m];
            float4 q = g_pts[base + m];
            pcx[j] = q.x; pcy[j] = q.y; pcz[j] = q.z;
            npc[j] = -q.w;
        }

        // ---- 64-deep feature dot, FFMA2, 4 rows x 2 col-pairs ----
        unsigned long long facc[4][2];
        #pragma unroll
        for (int i = 0; i < 4; i++) { facc[i][0] = 0ull; facc[i][1] = 0ull; }

        #pragma unroll
        for (int k0 = 0; k0 < 64; k0 += 4) {
            float4 av[4];
            #pragma unroll
            for (int i = 0; i < 4; i++)
                av[i] = *(const float4*)&As[ty * 4 + i][k0];
            const int bcol = ((tx ^ (k0 >> 2)) << 2);
            #pragma unroll
            for (int kk = 0; kk < 4; kk++) {
                ulonglong2 bq = *(const ulonglong2*)&Bs[(k0 + kk) * 64 + bcol];
                #pragma unroll
                for (int i = 0; i < 4; i++) {
                    float a = (kk == 0) ? av[i].x : (kk == 1) ? av[i].y
                             : (kk == 2) ? av[i].z : av[i].w;
                    unsigned long long aa = pack2(a);
                    fma2(facc[i][0], aa, bq.x);
                    fma2(facc[i][1], aa, bq.y);
                }
            }
        }

        // ---- epilogue: per-thread private online softmax (no shfl) ----
        #pragma unroll
        for (int i = 0; i < 4; i++) {
            float d[4];
            unpack2(d[0], d[1], facc[i][0]);
            unpack2(d[2], d[3], facc[i][1]);
            float fd[4], pd[4];
            #pragma unroll
            for (int j = 0; j < 4; j++) {
                fd[j] = fmaf(2.f, d[j], nra2[i] + nb[j]);
                float pdot = prx[i] * pcx[j];
                pdot = fmaf(pry[i], pcy[j], pdot);
                pdot = fmaf(prz[i], pcz[j], pdot);
                pd[j] = fmaf(2.f, pdot, nrp2[i] + npc[j]);
            }
            // point side: global max is 0 (diagonal), no tracking needed
            float e0 = __expf(pd[0]), e1 = __expf(pd[1]);
            float e2 = __expf(pd[2]), e3 = __expf(pd[3]);
            rpsum[i] += (e0 + e1) + (e2 + e3);
            float t = rT[i];
            t = fmaf(e0, fd[0], t); t = fmaf(e1, fd[1], t);
            t = fmaf(e2, fd[2], t); t = fmaf(e3, fd[3], t);
            rT[i] = t;
            // feature side: private online max
            float cm = fmaxf(fmaxf(fd[0], fd[1]), fmaxf(fd[2], fd[3]));
            float nf = fmaxf(rfmax[i], cm);
            float s = rfsum[i] * __expf(rfmax[i] - nf);
            s += __expf(fd[0] - nf); s += __expf(fd[1] - nf);
            s += __expf(fd[2] - nf); s += __expf(fd[3] - nf);
            rfsum[i] = s;
            rfmax[i] = nf;
        }
    }

    // ---- final merge across the 16 lanes of each row group ----
    float ce = 0.f;
    #pragma unroll
    for (int i = 0; i < 4; i++) {
        float M  = redmax16(rfmax[i]);
        float fs = redsum16(rfsum[i] * __expf(rfmax[i] - M));
        float Tt = redsum16(rT[i]);
        float Pp = redsum16(rpsum[i]);
        if (tx == 0) {
            int n = n0 + ty * 4 + i;
            ce += wts[base + n] * (M + logf(fs) - Tt / Pp);
        }
    }
    if (tx == 0) sred[ty] = ce;
    __syncthreads();
    if (tid == 0) {
        float s = 0.f;
        #pragma unroll
        for (int t = 0; t < 16; t++) s += sred[t];
        atomicAdd(&out[b], s);
    }
}

extern "C" void kernel_launch(void* const* d_in, const int* in_sizes, int n_in,
                              void* d_out, int out_size) {
    const float* points = (const float*)d_in[0];
    const float* f1     = (const float*)d_in[1];
    const float* f2     = (const float*)d_in[2];
    const float* w      = (const float*)d_in[3];
    float* out = (float*)d_out;

    int B = out_size / 2;                 // out = [ce_loss(B), reg(B)]
    int N = in_sizes[3] / B;              // weights is B*N
    int D = in_sizes[1] / (B * N);        // 64

    zero_k<<<1, 32>>>(out, out_size);
    init_norms<<<(B * N + 255) / 256, 256>>>(points, f1, f2, out, B, N, D);
    dim3 grid(N / 64, B);
    loss_main<<<grid, 256>>>(f1, f2, w, out, N);
}

// round 6
// speedup vs baseline: 3.1796x; 2.0613x over previous
#include <cuda_runtime.h>
#include <cuda_bf16.h>
#include <math.h>
#include <stdint.h>

#define FULLMASK 0xffffffffu
#define INV_SIGMA 200.0f
#define LOG2E 1.4426950408889634f
#define SQRT_LOG2E 1.2011224087864498f
#define LN2 0.6931471805599453f

// device scratch (no runtime allocation allowed)
__device__ float  g_a2[4 * 4096];    // log2e * |f1_n|^2
__device__ float  g_b2[4 * 4096];    // log2e * |f2_m|^2
__device__ float4 g_pts[4 * 4096];   // points*(200*sqrt(log2e)), w = |.|^2

// ---------------- helpers (base PTX only) ----------------
__device__ __forceinline__ float ex2f(float x) {
    float y; asm("ex2.approx.ftz.f32 %0, %1;" : "=f"(y) : "f"(x)); return y;
}
__device__ __forceinline__ float lg2f(float x) {
    float y; asm("lg2.approx.f32 %0, %1;" : "=f"(y) : "f"(x)); return y;
}
__device__ __forceinline__ uint32_t s2u(const void* p) {
    uint32_t a;
    asm("{ .reg .u64 t; cvta.to.shared.u64 t, %1; cvt.u32.u64 %0, t; }"
        : "=r"(a) : "l"(p));
    return a;
}
// pack two floats -> bf16x2 (first arg in LOW half = even-k element)
__device__ __forceinline__ uint32_t pkbf2(float lo, float hi) {
    uint32_t r;
    asm("cvt.rn.bf16x2.f32 %0, %1, %2;" : "=r"(r) : "f"(hi), "f"(lo));
    return r;
}
__device__ __forceinline__ float bflo(uint32_t p) { return __uint_as_float(p << 16); }
__device__ __forceinline__ float bfhi(uint32_t p) { return __uint_as_float(p & 0xffff0000u); }
// split (x,y) into bf16 hi pair + bf16 lo (residual) pair
__device__ __forceinline__ void split2(float x, float y, uint32_t& hw, uint32_t& lw) {
    hw = pkbf2(x, y);
    lw = pkbf2(x - bflo(hw), y - bfhi(hw));
}
__device__ __forceinline__ void ldmx4(uint32_t* r, uint32_t addr) {
    asm volatile("ldmatrix.sync.aligned.m8n8.x4.shared.b16 {%0,%1,%2,%3}, [%4];"
                 : "=r"(r[0]), "=r"(r[1]), "=r"(r[2]), "=r"(r[3]) : "r"(addr));
}
__device__ __forceinline__ void mma16816(float* d, const uint32_t* a,
                                         uint32_t b0, uint32_t b1) {
    asm volatile(
        "mma.sync.aligned.m16n8k16.row.col.f32.bf16.bf16.f32 "
        "{%0,%1,%2,%3}, {%4,%5,%6,%7}, {%8,%9}, {%0,%1,%2,%3};"
        : "+f"(d[0]), "+f"(d[1]), "+f"(d[2]), "+f"(d[3])
        : "r"(a[0]), "r"(a[1]), "r"(a[2]), "r"(a[3]), "r"(b0), "r"(b1));
}

// ---------------- small kernels ----------------
__global__ void zero_k(float* out, int n) {
    int i = threadIdx.x;
    if (i < n) out[i] = 0.0f;
}

__global__ void init_norms(const float* __restrict__ points,
                           const float* __restrict__ f1,
                           const float* __restrict__ f2,
                           float* __restrict__ out,
                           int B, int N, int D) {
    int idx = blockIdx.x * blockDim.x + threadIdx.x;
    if (idx >= B * N) return;
    int b = idx / N;
    const float4* pa = (const float4*)(f1 + (size_t)idx * D);
    const float4* pb = (const float4*)(f2 + (size_t)idx * D);
    float a2 = 0.f, b2 = 0.f;
    #pragma unroll 16
    for (int i = 0; i < 16; i++) {
        float4 v = pa[i];
        a2 = fmaf(v.x, v.x, a2); a2 = fmaf(v.y, v.y, a2);
        a2 = fmaf(v.z, v.z, a2); a2 = fmaf(v.w, v.w, a2);
        float4 u = pb[i];
        b2 = fmaf(u.x, u.x, b2); b2 = fmaf(u.y, u.y, b2);
        b2 = fmaf(u.z, u.z, b2); b2 = fmaf(u.w, u.w, b2);
    }
    g_a2[idx] = LOG2E * a2;
    g_b2[idx] = LOG2E * b2;
    const float SPT = INV_SIGMA * SQRT_LOG2E;
    float px = points[idx * 3 + 0] * SPT;
    float py = points[idx * 3 + 1] * SPT;
    float pz = points[idx * 3 + 2] * SPT;
    g_pts[idx] = make_float4(px, py, pz, px * px + py * py + pz * pz);

    float val = a2 + b2;   // raw for reg loss
    #pragma unroll
    for (int o = 16; o; o >>= 1) val += __shfl_xor_sync(FULLMASK, val, o);
    if ((threadIdx.x & 31) == 0)
        atomicAdd(&out[B + b], val / (float)(N * D));
}

// ---------------- main tensor-core kernel (mma.sync, base PTX) ----------------
// CTA: 128 rows, 8 warps (warp w owns rows 16w..16w+15), chunks of 128 cols.
// A fragments (bf16 hi/lo, 3-pass split) persist in registers.
// B chunk bf16 hi/lo in smem, 16B-chunk XOR swizzle -> conflict-free ldmatrix.
__global__ void __launch_bounds__(256, 1)
loss_mma(const float* __restrict__ f1, const float* __restrict__ f2,
         const float* __restrict__ wts, float* __restrict__ out, int N) {
    __shared__ __align__(16) uint32_t sBhi[128 * 32];   // 16KB
    __shared__ __align__(16) uint32_t sBlo[128 * 32];   // 16KB
    __shared__ float  sNb2[128];
    __shared__ float4 sCp[128];
    __shared__ float  sced[128];

    const int b   = blockIdx.y;
    const int n0  = blockIdx.x * 128;
    const int tid = threadIdx.x;
    const int w   = tid >> 5;
    const int L   = tid & 31;
    const int g   = L >> 2;
    const int t4  = L & 3;
    const size_t base = (size_t)b * N;

    // ---- A fragments (persist whole kernel) ----
    const int r0 = n0 + 16 * w + g, r1 = r0 + 8;
    uint32_t ahi[4][4], alo[4][4];
    {
        const float* A0 = f1 + (base + r0) * 64;
        const float* A1 = f1 + (base + r1) * 64;
        #pragma unroll
        for (int kt = 0; kt < 4; kt++) {
            int k0 = 16 * kt + 2 * t4;
            float2 x0 = *(const float2*)(A0 + k0);
            float2 x1 = *(const float2*)(A1 + k0);
            float2 x2 = *(const float2*)(A0 + k0 + 8);
            float2 x3 = *(const float2*)(A1 + k0 + 8);
            split2(x0.x * SQRT_LOG2E, x0.y * SQRT_LOG2E, ahi[kt][0], alo[kt][0]);
            split2(x1.x * SQRT_LOG2E, x1.y * SQRT_LOG2E, ahi[kt][1], alo[kt][1]);
            split2(x2.x * SQRT_LOG2E, x2.y * SQRT_LOG2E, ahi[kt][2], alo[kt][2]);
            split2(x3.x * SQRT_LOG2E, x3.y * SQRT_LOG2E, ahi[kt][3], alo[kt][3]);
        }
    }
    const float nra0 = -g_a2[base + r0], nra1 = -g_a2[base + r1];
    const float4 P0 = g_pts[base + r0], P1 = g_pts[base + r1];
    const float nP0 = -P0.w, nP1 = -P1.w;

    float M0 = -1e30f, M1 = -1e30f;
    float fs0 = 0.f, fs1 = 0.f, ps0 = 0.f, ps1 = 0.f, T0 = 0.f, T1 = 0.f;

    // ldmatrix lane addresses (byte), advanced by 1024 per coltile
    const uint32_t lr = (uint32_t)(L & 7), lt = (uint32_t)(L >> 3);
    const uint32_t bHi = s2u(sBhi), bLo = s2u(sBlo);
    const uint32_t adH1 = bHi + lr * 128 + ((lt ^ lr) << 4);
    const uint32_t adH2 = bHi + lr * 128 + (((lt + 4) ^ lr) << 4);
    const uint32_t adL1 = bLo + lr * 128 + ((lt ^ lr) << 4);
    const uint32_t adL2 = bLo + lr * 128 + (((lt + 4) ^ lr) << 4);

    // B chunk prefetch (thread: row rr, half hh of 64 k)
    const int rr = tid >> 1, hh = tid & 1;
    float4 bv[8];
    {
        const float4* src = (const float4*)(f2 + (base + rr) * 64 + 32 * hh);
        #pragma unroll
        for (int i = 0; i < 8; i++) bv[i] = src[i];
    }
    float nbp = 0.f; float4 cpp = make_float4(0, 0, 0, 0);
    if (tid < 128) { nbp = -g_b2[base + tid]; cpp = g_pts[base + tid]; }

    const int nCh = N >> 7;
    for (int c = 0; c < nCh; c++) {
        if (c) __syncthreads();
        // ---- store B chunk as bf16 hi/lo, swizzled ----
        #pragma unroll
        for (int q = 0; q < 4; q++) {
            float4 e0 = bv[2 * q], e1 = bv[2 * q + 1];
            uint32_t h0, l0, h1, l1, h2, l2, h3, l3;
            split2(e0.x * SQRT_LOG2E, e0.y * SQRT_LOG2E, h0, l0);
            split2(e0.z * SQRT_LOG2E, e0.w * SQRT_LOG2E, h1, l1);
            split2(e1.x * SQRT_LOG2E, e1.y * SQRT_LOG2E, h2, l2);
            split2(e1.z * SQRT_LOG2E, e1.w * SQRT_LOG2E, h3, l3);
            uint32_t cch = (uint32_t)(4 * hh + q);
            uint32_t off = (uint32_t)rr * 32 + ((cch ^ ((uint32_t)rr & 7)) << 2);
            *(uint4*)&sBhi[off] = make_uint4(h0, h1, h2, h3);
            *(uint4*)&sBlo[off] = make_uint4(l0, l1, l2, l3);
        }
        if (tid < 128) { sNb2[tid] = nbp; sCp[tid] = cpp; }
        __syncthreads();
        // prefetch next chunk
        if (c + 1 < nCh) {
            const float4* src = (const float4*)(f2 + (base + (c + 1) * 128 + rr) * 64 + 32 * hh);
            #pragma unroll
            for (int i = 0; i < 8; i++) bv[i] = src[i];
            if (tid < 128) {
                nbp = -g_b2[base + (c + 1) * 128 + tid];
                cpp = g_pts[base + (c + 1) * 128 + tid];
            }
        }

        // ---- 16 coltiles of 8 cols ----
        #pragma unroll 2
        for (int j = 0; j < 16; j++) {
            uint32_t off = (uint32_t)j << 10;
            uint32_t bh[8], bl[8];
            ldmx4(bh,     adH1 + off);
            ldmx4(bh + 4, adH2 + off);
            ldmx4(bl,     adL1 + off);
            ldmx4(bl + 4, adL2 + off);
            float d[4] = {0.f, 0.f, 0.f, 0.f};
            #pragma unroll
            for (int kt = 0; kt < 4; kt++) mma16816(d, ahi[kt], bh[2 * kt], bh[2 * kt + 1]);
            #pragma unroll
            for (int kt = 0; kt < 4; kt++) mma16816(d, ahi[kt], bl[2 * kt], bl[2 * kt + 1]);
            #pragma unroll
            for (int kt = 0; kt < 4; kt++) mma16816(d, alo[kt], bh[2 * kt], bh[2 * kt + 1]);

            // epilogue on 4 values: rows {r0, r1} x cols {ci, ci+1}
            int ci = 8 * j + 2 * t4;
            float2 nb2 = *(const float2*)&sNb2[ci];
            float4 Q0 = sCp[ci], Q1 = sCp[ci + 1];
            float fd0 = fmaf(2.f, d[0], nra0 + nb2.x);
            float fd1 = fmaf(2.f, d[1], nra0 + nb2.y);
            float fd2 = fmaf(2.f, d[2], nra1 + nb2.x);
            float fd3 = fmaf(2.f, d[3], nra1 + nb2.y);
            float pda = fmaf(2.f, fmaf(P0.x, Q0.x, fmaf(P0.y, Q0.y, P0.z * Q0.z)), nP0 - Q0.w);
            float pdb = fmaf(2.f, fmaf(P0.x, Q1.x, fmaf(P0.y, Q1.y, P0.z * Q1.z)), nP0 - Q1.w);
            float pdc = fmaf(2.f, fmaf(P1.x, Q0.x, fmaf(P1.y, Q0.y, P1.z * Q0.z)), nP1 - Q0.w);
            float pdd = fmaf(2.f, fmaf(P1.x, Q1.x, fmaf(P1.y, Q1.y, P1.z * Q1.z)), nP1 - Q1.w);
            float ea = ex2f(pda), eb = ex2f(pdb), ec = ex2f(pdc), ed = ex2f(pdd);
            ps0 += ea + eb;
            ps1 += ec + ed;
            T0 = fmaf(ea, fd0, fmaf(eb, fd1, T0));
            T1 = fmaf(ec, fd2, fmaf(ed, fd3, T1));
            float cm0 = fmaxf(fd0, fd1), cm1 = fmaxf(fd2, fd3);
            float Mn0 = fmaxf(M0, cm0),  Mn1 = fmaxf(M1, cm1);
            fs0 = fs0 * ex2f(M0 - Mn0) + ex2f(fd0 - Mn0) + ex2f(fd1 - Mn0);
            fs1 = fs1 * ex2f(M1 - Mn1) + ex2f(fd2 - Mn1) + ex2f(fd3 - Mn1);
            M0 = Mn0; M1 = Mn1;
        }
    }

    // ---- merge across the 4 lanes (t4) sharing each row ----
    #pragma unroll
    for (int off = 1; off <= 2; off <<= 1) {
        float Mo = __shfl_xor_sync(FULLMASK, M0, off);
        float fo = __shfl_xor_sync(FULLMASK, fs0, off);
        float Mn = fmaxf(M0, Mo);
        fs0 = fs0 * ex2f(M0 - Mn) + fo * ex2f(Mo - Mn); M0 = Mn;
        ps0 += __shfl_xor_sync(FULLMASK, ps0, off);
        T0  += __shfl_xor_sync(FULLMASK, T0, off);
        Mo = __shfl_xor_sync(FULLMASK, M1, off);
        fo = __shfl_xor_sync(FULLMASK, fs1, off);
        Mn = fmaxf(M1, Mo);
        fs1 = fs1 * ex2f(M1 - Mn) + fo * ex2f(Mo - Mn); M1 = Mn;
        ps1 += __shfl_xor_sync(FULLMASK, ps1, off);
        T1  += __shfl_xor_sync(FULLMASK, T1, off);
    }
    if (t4 == 0) {
        sced[16 * w + g]     = wts[base + r0] * LN2 * (M0 + lg2f(fs0) - T0 / ps0);
        sced[16 * w + g + 8] = wts[base + r1] * LN2 * (M1 + lg2f(fs1) - T1 / ps1);
    }
    __syncthreads();
    if (tid < 128) {
        float v = sced[tid];
        #pragma unroll
        for (int o = 16; o; o >>= 1) v += __shfl_xor_sync(FULLMASK, v, o);
        if (L == 0) atomicAdd(&out[b], v);
    }
}

extern "C" void kernel_launch(void* const* d_in, const int* in_sizes, int n_in,
                              void* d_out, int out_size) {
    const float* points = (const float*)d_in[0];
    const float* f1     = (const float*)d_in[1];
    const float* f2     = (const float*)d_in[2];
    const float* w      = (const float*)d_in[3];
    float* out = (float*)d_out;

    int B = out_size / 2;            // out = [ce_loss(B), reg(B)]
    int N = in_sizes[3] / B;         // weights is B*N
    int D = in_sizes[1] / (B * N);   // 64

    zero_k<<<1, 32>>>(out, out_size);
    init_norms<<<(B * N + 255) / 256, 256>>>(points, f1, f2, out, B, N, D);
    dim3 grid(N / 128, B);
    loss_mma<<<grid, 256>>>(f1, f2, w, out, N);
}

// round 12
// speedup vs baseline: 3.7503x; 1.1795x over previous
#include <cuda_runtime.h>
#include <cuda_bf16.h>
#include <math.h>
#include <stdint.h>

#define FULLMASK 0xffffffffu
#define INV_SIGMA 200.0f
#define LOG2E 1.4426950408889634f
#define SQRT_LOG2E 1.2011224087864498f
#define LN2 0.6931471805599453f

// device scratch (no runtime allocation allowed)
__device__ float  g_a2[4 * 4096];          // log2e * |f1_n|^2
__device__ float  g_b2[4 * 4096];          // log2e * |f2_m|^2
__device__ float4 g_pts[4 * 4096];         // points*(200*sqrt(log2e)), w=|.|^2
// pre-split f2 (bf16 hi/lo), stored per (b,chunk) as the exact swizzled
// 128x32-uint32 smem image -> main loop copies it linearly via cp.async.
__device__ uint32_t gBhi[4 * 32 * 4096];   // 2MB
__device__ uint32_t gBlo[4 * 32 * 4096];   // 2MB

// ---------------- helpers (base PTX only) ----------------
__device__ __forceinline__ float ex2f(float x) {
    float y; asm("ex2.approx.ftz.f32 %0, %1;" : "=f"(y) : "f"(x)); return y;
}
__device__ __forceinline__ float lg2f(float x) {
    float y; asm("lg2.approx.f32 %0, %1;" : "=f"(y) : "f"(x)); return y;
}
__device__ __forceinline__ uint32_t s2u(const void* p) {
    uint32_t a;
    asm("{ .reg .u64 t; cvta.to.shared.u64 t, %1; cvt.u32.u64 %0, t; }"
        : "=r"(a) : "l"(p));
    return a;
}
__device__ __forceinline__ uint32_t pkbf2(float lo, float hi) {
    uint32_t r;
    asm("cvt.rn.bf16x2.f32 %0, %1, %2;" : "=r"(r) : "f"(hi), "f"(lo));
    return r;
}
__device__ __forceinline__ float bflo(uint32_t p) { return __uint_as_float(p << 16); }
__device__ __forceinline__ float bfhi(uint32_t p) { return __uint_as_float(p & 0xffff0000u); }
__device__ __forceinline__ void split2(float x, float y, uint32_t& hw, uint32_t& lw) {
    hw = pkbf2(x, y);
    lw = pkbf2(x - bflo(hw), y - bfhi(hw));
}
__device__ __forceinline__ void ldmx4(uint32_t* r, uint32_t addr) {
    asm volatile("ldmatrix.sync.aligned.m8n8.x4.shared.b16 {%0,%1,%2,%3}, [%4];"
                 : "=r"(r[0]), "=r"(r[1]), "=r"(r[2]), "=r"(r[3]) : "r"(addr));
}
__device__ __forceinline__ void mma16816(float* d, const uint32_t* a,
                                         uint32_t b0, uint32_t b1) {
    asm volatile(
        "mma.sync.aligned.m16n8k16.row.col.f32.bf16.bf16.f32 "
        "{%0,%1,%2,%3}, {%4,%5,%6,%7}, {%8,%9}, {%0,%1,%2,%3};"
        : "+f"(d[0]), "+f"(d[1]), "+f"(d[2]), "+f"(d[3])
        : "r"(a[0]), "r"(a[1]), "r"(a[2]), "r"(a[3]), "r"(b0), "r"(b1));
}
__device__ __forceinline__ void cpa16(uint32_t s, const void* g) {
    asm volatile("cp.async.cg.shared.global [%0], [%1], 16;"
                 :: "r"(s), "l"(g) : "memory");
}
#define CP_COMMIT() asm volatile("cp.async.commit_group;" ::: "memory")
#define CP_WAIT1()  asm volatile("cp.async.wait_group 1;" ::: "memory")
#define CP_WAIT0()  asm volatile("cp.async.wait_group 0;" ::: "memory")

// ---------------- small kernels ----------------
__global__ void zero_k(float* out, int n) {
    int i = threadIdx.x;
    if (i < n) out[i] = 0.0f;
}

__global__ void init_norms(const float* __restrict__ points,
                           const float* __restrict__ f1,
                           const float* __restrict__ f2,
                           float* __restrict__ out,
                           int B, int N, int D) {
    int idx = blockIdx.x * blockDim.x + threadIdx.x;
    if (idx >= B * N) return;
    int b = idx / N;
    const float4* pa = (const float4*)(f1 + (size_t)idx * D);
    const float4* pb = (const float4*)(f2 + (size_t)idx * D);
    float a2 = 0.f, b2 = 0.f;
    #pragma unroll 16
    for (int i = 0; i < 16; i++) {
        float4 v = pa[i];
        a2 = fmaf(v.x, v.x, a2); a2 = fmaf(v.y, v.y, a2);
        a2 = fmaf(v.z, v.z, a2); a2 = fmaf(v.w, v.w, a2);
        float4 u = pb[i];
        b2 = fmaf(u.x, u.x, b2); b2 = fmaf(u.y, u.y, b2);
        b2 = fmaf(u.z, u.z, b2); b2 = fmaf(u.w, u.w, b2);
    }
    g_a2[idx] = LOG2E * a2;
    g_b2[idx] = LOG2E * b2;
    const float SPT = INV_SIGMA * SQRT_LOG2E;
    float px = points[idx * 3 + 0] * SPT;
    float py = points[idx * 3 + 1] * SPT;
    float pz = points[idx * 3 + 2] * SPT;
    g_pts[idx] = make_float4(px, py, pz, px * px + py * py + pz * pz);

    float val = a2 + b2;   // raw for reg loss
    #pragma unroll
    for (int o = 16; o; o >>= 1) val += __shfl_xor_sync(FULLMASK, val, o);
    if ((threadIdx.x & 31) == 0)
        atomicAdd(&out[B + b], val / (float)(N * D));
}

// Pre-split f2 into bf16 hi/lo swizzled chunk images.
// Work item = (b, chunk c, row rr, 16B-chunk cch): 8 floats -> 4+4 uint32.
__global__ void bsplit_k(const float* __restrict__ f2, int total) {
    int idx = blockIdx.x * blockDim.x + threadIdx.x;
    if (idx >= total) return;
    int cch = idx & 7;
    int rr  = (idx >> 3) & 127;
    int img = idx >> 10;           // b*32 + c
    const float4* src = (const float4*)(f2 + ((size_t)img * 128 + rr) * 64 + cch * 8);
    float4 e0 = src[0], e1 = src[1];
    uint32_t h0, l0, h1, l1, h2, l2, h3, l3;
    split2(e0.x * SQRT_LOG2E, e0.y * SQRT_LOG2E, h0, l0);
    split2(e0.z * SQRT_LOG2E, e0.w * SQRT_LOG2E, h1, l1);
    split2(e1.x * SQRT_LOG2E, e1.y * SQRT_LOG2E, h2, l2);
    split2(e1.z * SQRT_LOG2E, e1.w * SQRT_LOG2E, h3, l3);
    uint32_t off = (uint32_t)img * 4096 + (uint32_t)rr * 32
                 + (((uint32_t)cch ^ ((uint32_t)rr & 7)) << 2);
    *(uint4*)&gBhi[off] = make_uint4(h0, h1, h2, h3);
    *(uint4*)&gBlo[off] = make_uint4(l0, l1, l2, l3);
}

// ---------------- main tensor-core kernel ----------------
// CTA: 128 rows, 8 warps; chunks of 128 cols. A frags persist in registers.
// B chunk images cp.async'd into double-buffered dynamic smem.
__global__ void __launch_bounds__(256, 1)
loss_mma(const float* __restrict__ f1,
         const float* __restrict__ wts, float* __restrict__ out, int N) {
    extern __shared__ __align__(16) uint32_t dynS[];   // [2][8192]: hi(4096)+lo(4096) per buf
    __shared__ float  sNb2[2][128];
    __shared__ float4 sCp[2][128];
    __shared__ float  sced[128];

    const int b   = blockIdx.y;
    const int n0  = blockIdx.x * 128;
    const int tid = threadIdx.x;
    const int w   = tid >> 5;
    const int L   = tid & 31;
    const int g   = L >> 2;
    const int t4  = L & 3;
    const size_t base = (size_t)b * N;
    const int nCh = N >> 7;
    const uint32_t sBase = s2u(dynS);

    // prologue copies for chunks 0 and 1
    {
        const uint4* gh = (const uint4*)gBhi + (size_t)(b * 32) * 1024;
        const uint4* gl = (const uint4*)gBlo + (size_t)(b * 32) * 1024;
        #pragma unroll
        for (int i = 0; i < 4; i++) {
            int u = i * 256 + tid;
            cpa16(sBase + u * 16, gh + u);
            cpa16(sBase + 16384 + u * 16, gl + u);
        }
        CP_COMMIT();
        #pragma unroll
        for (int i = 0; i < 4; i++) {
            int u = i * 256 + tid;
            cpa16(sBase + 32768 + u * 16, gh + 1024 + u);
            cpa16(sBase + 49152 + u * 16, gl + 1024 + u);
        }
        CP_COMMIT();
    }
    if (tid < 128) {
        sNb2[0][tid] = -g_b2[base + tid];
        sCp[0][tid]  = g_pts[base + tid];
        sNb2[1][tid] = -g_b2[base + 128 + tid];
        sCp[1][tid]  = g_pts[base + 128 + tid];
    }

    // ---- A fragments (persist whole kernel) ----
    const int r0 = n0 + 16 * w + g, r1 = r0 + 8;
    uint32_t ahi[4][4], alo[4][4];
    {
        const float* A0 = f1 + (base + r0) * 64;
        const float* A1 = f1 + (base + r1) * 64;
        #pragma unroll
        for (int kt = 0; kt < 4; kt++) {
            int k0 = 16 * kt + 2 * t4;
            float2 x0 = *(const float2*)(A0 + k0);
            float2 x1 = *(const float2*)(A1 + k0);
            float2 x2 = *(const float2*)(A0 + k0 + 8);
            float2 x3 = *(const float2*)(A1 + k0 + 8);
            split2(x0.x * SQRT_LOG2E, x0.y * SQRT_LOG2E, ahi[kt][0], alo[kt][0]);
            split2(x1.x * SQRT_LOG2E, x1.y * SQRT_LOG2E, ahi[kt][1], alo[kt][1]);
            split2(x2.x * SQRT_LOG2E, x2.y * SQRT_LOG2E, ahi[kt][2], alo[kt][2]);
            split2(x3.x * SQRT_LOG2E, x3.y * SQRT_LOG2E, ahi[kt][3], alo[kt][3]);
        }
    }
    const float nra0 = -g_a2[base + r0], nra1 = -g_a2[base + r1];
    const float4 P0 = g_pts[base + r0], P1 = g_pts[base + r1];
    const float nP0 = -P0.w, nP1 = -P1.w;

    float M0 = -1e30f, M1 = -1e30f;
    float fs0 = 0.f, fs1 = 0.f, ps0 = 0.f, ps1 = 0.f, T0 = 0.f, T1 = 0.f;

    // ldmatrix lane addresses (per buffer, bytes)
    const uint32_t lr = (uint32_t)(L & 7), lt = (uint32_t)(L >> 3);
    const uint32_t aH1 = sBase + lr * 128 + ((lt ^ lr) << 4);
    const uint32_t aH2 = sBase + lr * 128 + (((lt + 4) ^ lr) << 4);

    for (int c = 0; c < nCh; c++) {
        if (c == nCh - 1) { CP_WAIT0(); } else { CP_WAIT1(); }
        __syncthreads();
        const int buf = c & 1;
        const uint32_t boff = (uint32_t)buf << 15;   // 32KB per buffer

        // ---- 16 coltiles of 8 cols ----
        #pragma unroll 2
        for (int j = 0; j < 16; j++) {
            uint32_t off = boff + ((uint32_t)j << 10);
            uint32_t bh[8], bl[8];
            ldmx4(bh,     aH1 + off);
            ldmx4(bh + 4, aH2 + off);
            ldmx4(bl,     aH1 + 16384 + off);
            ldmx4(bl + 4, aH2 + 16384 + off);
            float dhh[4] = {0.f, 0.f, 0.f, 0.f};
            float dhl[4] = {0.f, 0.f, 0.f, 0.f};
            float dlh[4] = {0.f, 0.f, 0.f, 0.f};
            #pragma unroll
            for (int kt = 0; kt < 4; kt++) {
                mma16816(dhh, ahi[kt], bh[2 * kt], bh[2 * kt + 1]);
                mma16816(dhl, ahi[kt], bl[2 * kt], bl[2 * kt + 1]);
                mma16816(dlh, alo[kt], bh[2 * kt], bh[2 * kt + 1]);
            }
            float d0 = dhh[0] + (dhl[0] + dlh[0]);
            float d1 = dhh[1] + (dhl[1] + dlh[1]);
            float d2 = dhh[2] + (dhl[2] + dlh[2]);
            float d3 = dhh[3] + (dhl[3] + dlh[3]);

            // epilogue on 4 values: rows {r0,r1} x cols {ci, ci+1}
            int ci = 8 * j + 2 * t4;
            float2 nb2 = *(const float2*)&sNb2[buf][ci];
            float4 Q0 = sCp[buf][ci], Q1 = sCp[buf][ci + 1];
            float fd0 = fmaf(2.f, d0, nra0 + nb2.x);
            float fd1 = fmaf(2.f, d1, nra0 + nb2.y);
            float fd2 = fmaf(2.f, d2, nra1 + nb2.x);
            float fd3 = fmaf(2.f, d3, nra1 + nb2.y);
            float pda = fmaf(2.f, fmaf(P0.x, Q0.x, fmaf(P0.y, Q0.y, P0.z * Q0.z)), nP0 - Q0.w);
            float pdb = fmaf(2.f, fmaf(P0.x, Q1.x, fmaf(P0.y, Q1.y, P0.z * Q1.z)), nP0 - Q1.w);
            float pdc = fmaf(2.f, fmaf(P1.x, Q0.x, fmaf(P1.y, Q0.y, P1.z * Q0.z)), nP1 - Q0.w);
            float pdd = fmaf(2.f, fmaf(P1.x, Q1.x, fmaf(P1.y, Q1.y, P1.z * Q1.z)), nP1 - Q1.w);
            float ea = ex2f(pda), eb = ex2f(pdb), ec = ex2f(pdc), ed = ex2f(pdd);
            ps0 += ea + eb;
            ps1 += ec + ed;
            T0 = fmaf(ea, fd0, fmaf(eb, fd1, T0));
            T1 = fmaf(ec, fd2, fmaf(ed, fd3, T1));
            float cm0 = fmaxf(fd0, fd1), cm1 = fmaxf(fd2, fd3);
            float Mn0 = fmaxf(M0, cm0),  Mn1 = fmaxf(M1, cm1);
            fs0 = fs0 * ex2f(M0 - Mn0) + ex2f(fd0 - Mn0) + ex2f(fd1 - Mn0);
            fs1 = fs1 * ex2f(M1 - Mn1) + ex2f(fd2 - Mn1) + ex2f(fd3 - Mn1);
            M0 = Mn0; M1 = Mn1;
        }

        __syncthreads();   // all readers done with buf before overwriting it
        if (c + 2 < nCh) {
            const uint4* gh = (const uint4*)gBhi + (size_t)(b * 32 + c + 2) * 1024;
            const uint4* gl = (const uint4*)gBlo + (size_t)(b * 32 + c + 2) * 1024;
            #pragma unroll
            for (int i = 0; i < 4; i++) {
                int u = i * 256 + tid;
                cpa16(sBase + boff + u * 16, gh + u);
                cpa16(sBase + boff + 16384 + u * 16, gl + u);
            }
            CP_COMMIT();
            if (tid < 128) {
                sNb2[buf][tid] = -g_b2[base + (c + 2) * 128 + tid];
                sCp[buf][tid]  = g_pts[base + (c + 2) * 128 + tid];
            }
        }
    }

    // ---- merge across the 4 lanes (t4) sharing each row ----
    #pragma unroll
    for (int off = 1; off <= 2; off <<= 1) {
        float Mo = __shfl_xor_sync(FULLMASK, M0, off);
        float fo = __shfl_xor_sync(FULLMASK, fs0, off);
        float Mn = fmaxf(M0, Mo);
        fs0 = fs0 * ex2f(M0 - Mn) + fo * ex2f(Mo - Mn); M0 = Mn;
        ps0 += __shfl_xor_sync(FULLMASK, ps0, off);
        T0  += __shfl_xor_sync(FULLMASK, T0, off);
        Mo = __shfl_xor_sync(FULLMASK, M1, off);
        fo = __shfl_xor_sync(FULLMASK, fs1, off);
        Mn = fmaxf(M1, Mo);
        fs1 = fs1 * ex2f(M1 - Mn) + fo * ex2f(Mo - Mn); M1 = Mn;
        ps1 += __shfl_xor_sync(FULLMASK, ps1, off);
        T1  += __shfl_xor_sync(FULLMASK, T1, off);
    }
    if (t4 == 0) {
        sced[16 * w + g]     = wts[base + r0] * LN2 * (M0 + lg2f(fs0) - T0 / ps0);
        sced[16 * w + g + 8] = wts[base + r1] * LN2 * (M1 + lg2f(fs1) - T1 / ps1);
    }
    __syncthreads();
    if (tid < 128) {
        float v = sced[tid];
        #pragma unroll
        for (int o = 16; o; o >>= 1) v += __shfl_xor_sync(FULLMASK, v, o);
        if (L == 0) atomicAdd(&out[b], v);
    }
}

extern "C" void kernel_launch(void* const* d_in, const int* in_sizes, int n_in,
                              void* d_out, int out_size) {
    const float* points = (const float*)d_in[0];
    const float* f1     = (const float*)d_in[1];
    const float* f2     = (const float*)d_in[2];
    const float* w      = (const float*)d_in[3];
    float* out = (float*)d_out;

    int B = out_size / 2;            // out = [ce_loss(B), reg(B)]
    int N = in_sizes[3] / B;         // weights is B*N
    int D = in_sizes[1] / (B * N);   // 64

    static int smemSet = 0;
    if (!smemSet) {
        cudaFuncSetAttribute(loss_mma, cudaFuncAttributeMaxDynamicSharedMemorySize,
                             65536);
        smemSet = 1;
    }

    zero_k<<<1, 32>>>(out, out_size);
    init_norms<<<(B * N + 255) / 256, 256>>>(points, f1, f2, out, B, N, D);
    int total = B * (N / 128) * 1024;
    bsplit_k<<<(total + 255) / 256, 256>>>(f2, total);
    dim3 grid(N / 128, B);
    loss_mma<<<grid, 256, 65536>>>(f1, w, out, N);
}